// round 14
// baseline (speedup 1.0000x reference)
#include <cuda_runtime.h>
#include <cstdint>

#define NS 512
#define NV 32000
#define NB 16
#define NT 128

// ---- scratch (no cudaMalloc allowed) ----
__device__ float g_lse_em[NS];
__device__ float g_pi[NS];
__device__ float g_PT[NS * NS];          // PT[c][s] = softmax(tm)[s][c]
__device__ float g_L[NB];                // per-batch log-likelihood

// ---- helpers ----
__device__ __forceinline__ unsigned smem_u32(const void* p) {
    return (unsigned)__cvta_generic_to_shared(p);
}
__device__ __forceinline__ unsigned mapa_u32(unsigned local, unsigned rank) {
    unsigned r;
    asm("mapa.shared::cluster.u32 %0, %1, %2;" : "=r"(r) : "r"(local), "r"(rank));
    return r;
}
#define MBAR_INIT(mb, cnt) \
    asm volatile("mbarrier.init.shared.b64 [%0], %1;" :: "r"(mb), "r"(cnt) : "memory")
#define MBAR_EXPECT_TX(mb, bytes) \
    asm volatile("mbarrier.arrive.expect_tx.shared.b64 _, [%0], %1;" :: "r"(mb), "r"(bytes) : "memory")
// HW-sleep wait (suspend hint keeps spinners off the SMEM port)
#define MBAR_WAIT_CLUSTER(mb, parity) do {                                                       \
    asm volatile("{\n\t.reg .pred P;\n\tW%=:\n\t"                                                \
        "mbarrier.try_wait.parity.acquire.cluster.shared::cta.b64 P, [%0], %1, 0x989680;\n\t"    \
        "@!P bra W%=;\n\t}" :: "r"(mb), "r"(parity) : "memory");                                 \
} while (0)
__device__ __forceinline__ void st_async_v4(unsigned raddr, float4 v, unsigned rmbar) {
    asm volatile(
        "st.async.shared::cluster.mbarrier::complete_tx::bytes.v4.f32 "
        "[%0], {%1, %2, %3, %4}, [%5];"
        :: "r"(raddr), "f"(v.x), "f"(v.y), "f"(v.z), "f"(v.w), "r"(rmbar) : "memory");
}
// packed f32x2 math
#define FMA2(d, a, b, c) \
    asm("fma.rn.f32x2 %0, %1, %2, %3;" : "=l"(d) : "l"(a), "l"(b), "l"(c))
#define ADD2(d, a, b) \
    asm("add.rn.f32x2 %0, %1, %2;" : "=l"(d) : "l"(a), "l"(b))
__device__ __forceinline__ float hadd2(unsigned long long v) {
    float lo, hi;
    asm("mov.b64 {%0, %1}, %2;" : "=f"(lo), "=f"(hi) : "l"(v));
    return lo + hi;
}

// ===================== K1: row logsumexp of em [512, 32000] =====================
__global__ void k_lse_em(const float* __restrict__ em) {
    const int row = blockIdx.x;
    const float4* r = (const float4*)(em + (size_t)row * NV);
    const int n4 = NV / 4;  // 8000

    __shared__ float sm[8];

    float m = -1e30f;
    for (int i = threadIdx.x; i < n4; i += blockDim.x) {
        float4 x = r[i];
        m = fmaxf(m, fmaxf(fmaxf(x.x, x.y), fmaxf(x.z, x.w)));
    }
    #pragma unroll
    for (int o = 16; o; o >>= 1) m = fmaxf(m, __shfl_xor_sync(~0u, m, o));
    if ((threadIdx.x & 31) == 0) sm[threadIdx.x >> 5] = m;
    __syncthreads();
    if (threadIdx.x < 32) {
        float mm = (threadIdx.x < (blockDim.x >> 5)) ? sm[threadIdx.x] : -1e30f;
        #pragma unroll
        for (int o = 4; o; o >>= 1) mm = fmaxf(mm, __shfl_xor_sync(~0u, mm, o));
        if (threadIdx.x == 0) sm[0] = mm;
    }
    __syncthreads();
    m = sm[0];
    __syncthreads();

    float s = 0.f;
    for (int i = threadIdx.x; i < n4; i += blockDim.x) {
        float4 x = r[i];
        s += __expf(x.x - m) + __expf(x.y - m) + __expf(x.z - m) + __expf(x.w - m);
    }
    #pragma unroll
    for (int o = 16; o; o >>= 1) s += __shfl_xor_sync(~0u, s, o);
    if ((threadIdx.x & 31) == 0) sm[threadIdx.x >> 5] = s;
    __syncthreads();
    if (threadIdx.x == 0) {
        float tot = 0.f;
        for (int wi = 0; wi < (blockDim.x >> 5); wi++) tot += sm[wi];
        g_lse_em[row] = m + __logf(tot);
    }
}

// ===================== K2: P^T = softmax(tm) transposed; pi = softmax(p) ========
__global__ void k_tm_pi(const float* __restrict__ tm, const float* __restrict__ p) {
    __shared__ float sm[4];
    __shared__ float red;
    const int tid = threadIdx.x;  // 128 threads

    const float* src = (blockIdx.x < NS) ? (tm + (size_t)blockIdx.x * NS) : p;

    float m = -1e30f;
    #pragma unroll
    for (int k = 0; k < 4; k++) m = fmaxf(m, src[tid + 128 * k]);
    #pragma unroll
    for (int o = 16; o; o >>= 1) m = fmaxf(m, __shfl_xor_sync(~0u, m, o));
    if ((tid & 31) == 0) sm[tid >> 5] = m;
    __syncthreads();
    if (tid == 0) red = fmaxf(fmaxf(sm[0], sm[1]), fmaxf(sm[2], sm[3]));
    __syncthreads();
    m = red;

    float s = 0.f;
    #pragma unroll
    for (int k = 0; k < 4; k++) s += __expf(src[tid + 128 * k] - m);
    #pragma unroll
    for (int o = 16; o; o >>= 1) s += __shfl_xor_sync(~0u, s, o);
    if ((tid & 31) == 0) sm[tid >> 5] = s;
    __syncthreads();
    if (tid == 0) red = m + __logf(sm[0] + sm[1] + sm[2] + sm[3]);
    __syncthreads();
    const float lse = red;

    if (blockIdx.x < NS) {
        const int row = blockIdx.x;  // source state s
        #pragma unroll
        for (int k = 0; k < 4; k++) {
            int c = tid + 128 * k;   // dest state
            g_PT[(size_t)c * NS + row] = __expf(src[c] - lse);
        }
    } else {
        #pragma unroll
        for (int k = 0; k < 4; k++) {
            int i = tid + 128 * k;
            g_pi[i] = __expf(p[i] - lse);
        }
    }
}

// ===================== K4: clustered scaled-forward recurrence ==================
// R12 core (best known: 221.7us) + ONE change: the emission gather is fused in
// (k_gather and g_E deleted). Each warp loads its 4 em values directly each
// step (broadcast LDG, L2-hot after k_lse_em) and applies exp inline; consumed
// ~500cyc later at the push, so the chain is latency-covered.
__global__ void __cluster_dims__(8, 1, 1) __launch_bounds__(512, 1)
k_forward(const float* __restrict__ em, const int* __restrict__ ids) {
    __shared__ __align__(16) float buf[2][NS];
    __shared__ __align__(8) unsigned long long mbars[2];

    const int tid = threadIdx.x;
    const int w = tid >> 5;
    const int l = tid & 31;
    unsigned rank;
    asm("mov.u32 %0, %%cluster_ctarank;" : "=r"(rank));
    const int g = blockIdx.x >> 3;                 // batch / cluster id
    const int colbase = (int)rank * 64 + w * 4;    // this warp's 4 columns

    // --- P^T chunk into packed registers ---
    unsigned long long Pa[4][4], Pb[4][4];
    #pragma unroll
    for (int j = 0; j < 4; j++)
        #pragma unroll
        for (int k = 0; k < 4; k++) {
            ulonglong2 pp = *(const ulonglong2*)&g_PT[(size_t)(colbase + j) * NS + 4 * l + 128 * k];
            Pa[j][k] = pp.x;
            Pb[j][k] = pp.y;
        }

    const unsigned mb0 = smem_u32(&mbars[0]);
    const unsigned mb1 = smem_u32(&mbars[1]);
    if (tid == 0) { MBAR_INIT(mb0, 1); MBAR_INIT(mb1, 1); }

    const int idsbase = g * NT;
    // lse for this warp's 4 columns (16B aligned: colbase % 4 == 0)
    const float4 lse4 = *(const float4*)&g_lse_em[colbase];

    // --- t = 0: every CTA computes the full v0 = pi * E0 locally (fused gather) ---
    {
        int id0 = ids[idsbase];
        id0 = (id0 < 0) ? 0 : ((id0 >= NV) ? NV - 1 : id0);
        const float e0 = __expf(__ldg(&em[(size_t)tid * NV + id0]) - g_lse_em[tid]);
        buf[0][tid] = g_pi[tid] * e0;
    }
    __syncthreads();
    // peers' mbarriers must be initialized before any st.async targets them
    asm volatile("barrier.cluster.arrive.aligned;" ::: "memory");
    asm volatile("barrier.cluster.wait.aligned;"   ::: "memory");

    // --- per-lane remote addresses (lanes 0..7 push to peer = lane index) ---
    unsigned rbuf = 0, rmb0 = 0, rmb1 = 0;
    if (l < 8) {
        rbuf = mapa_u32(smem_u32(&buf[0][0]), (unsigned)l);
        rmb0 = mapa_u32(mb0, (unsigned)l);
        rmb1 = mapa_u32(mb1, (unsigned)l);
    }

    int ph0 = 0, ph1 = 0;
    float L = 0.f;

    for (int t = 1; t < NT; t++) {
        const int sp = (t - 1) & 1;   // slot holding v_{t-1}
        const int sc = t & 1;         // slot receiving v_t

        // wait for v_{t-1}: ONLY warp 0 polls the mbarrier; bar.sync releases
        // (and memory-orders, cumulatively) the other 15 warps.
        if (t >= 2) {
            if (w == 0) {
                if (sp) MBAR_WAIT_CLUSTER(mb1, ph1);
                else    MBAR_WAIT_CLUSTER(mb0, ph0);
            }
            __syncthreads();
        }
        // arm this step's receive barrier (2048 B = 8 ranks x 16 warps x 16 B)
        if (tid == 0) MBAR_EXPECT_TX(sc ? mb1 : mb0, 2048u);

        // fused emission gather for THIS step's 4 columns (broadcast LDG,
        // L2-hot; exp chain ~300cyc, consumed at the push ~500cyc later)
        int idt = ids[idsbase + t];
        idt = (idt < 0) ? 0 : ((idt >= NV) ? NV - 1 : idt);
        const size_t cb = (size_t)colbase * NV + (size_t)idt;
        float4 e4;
        e4.x = __expf(__ldg(&em[cb])                  - lse4.x);
        e4.y = __expf(__ldg(&em[cb + NV])             - lse4.y);
        e4.z = __expf(__ldg(&em[cb + 2 * (size_t)NV]) - lse4.z);
        e4.w = __expf(__ldg(&em[cb + 3 * (size_t)NV]) - lse4.w);

        // packed dot over the 512-vector + packed S_prev sum
        const float* cur = buf[sp];
        unsigned long long acc0 = 0, acc1 = 0, acc2 = 0, acc3 = 0, ssp = 0;
        #pragma unroll
        for (int k = 0; k < 4; k++) {
            ulonglong2 aa = *(const ulonglong2*)&cur[4 * l + 128 * k];
            FMA2(acc0, aa.x, Pa[0][k], acc0); FMA2(acc0, aa.y, Pb[0][k], acc0);
            FMA2(acc1, aa.x, Pa[1][k], acc1); FMA2(acc1, aa.y, Pb[1][k], acc1);
            FMA2(acc2, aa.x, Pa[2][k], acc2); FMA2(acc2, aa.y, Pb[2][k], acc2);
            FMA2(acc3, aa.x, Pa[3][k], acc3); FMA2(acc3, aa.y, Pb[3][k], acc3);
            ADD2(ssp, ssp, aa.x); ADD2(ssp, ssp, aa.y);
        }
        float a0 = hadd2(acc0), a1 = hadd2(acc1), a2 = hadd2(acc2), a3 = hadd2(acc3);
        float ss = hadd2(ssp);

        // reduce-scatter butterfly: octet o (= l>>3) ends holding full acc_o
        float p0 = (l & 16) ? a2 : a0;
        float q0 = (l & 16) ? a0 : a2;
        float p1 = (l & 16) ? a3 : a1;
        float q1 = (l & 16) ? a1 : a3;
        p0 += __shfl_xor_sync(~0u, q0, 16);
        p1 += __shfl_xor_sync(~0u, q1, 16);
        float pp = (l & 8) ? p1 : p0;
        float qq = (l & 8) ? p0 : p1;
        pp += __shfl_xor_sync(~0u, qq, 8);
        pp += __shfl_xor_sync(~0u, pp, 4);
        pp += __shfl_xor_sync(~0u, pp, 2);
        pp += __shfl_xor_sync(~0u, pp, 1);
        // regather: every lane builds (a0,a1,a2,a3) from octet representatives
        const int lb = l & 7;
        const float v0 = __shfl_sync(~0u, pp, lb);
        const float v1 = __shfl_sync(~0u, pp, 8 + lb);
        const float v2 = __shfl_sync(~0u, pp, 16 + lb);
        const float v3 = __shfl_sync(~0u, pp, 24 + lb);
        // full butterfly for ss (S_{t-1}; every lane needs it)
        #pragma unroll
        for (int o = 16; o; o >>= 1) ss += __shfl_xor_sync(~0u, ss, o);
        const float invS = __fdividef(1.f, ss);

        // push this warp's 4 scaled columns to all 8 CTAs (lane r -> peer r)
        if (l < 8) {
            float4 v;
            v.x = v0 * invS * e4.x;
            v.y = v1 * invS * e4.y;
            v.z = v2 * invS * e4.z;
            v.w = v3 * invS * e4.w;
            const unsigned daddr = rbuf + (unsigned)((sc * NS + colbase) * 4);
            st_async_v4(daddr, v, sc ? rmb1 : rmb0);
        }
        if (rank == 0 && tid == 0) L += __logf(ss);
        if (t >= 2) { if (sp) ph1 ^= 1; else ph0 ^= 1; }
    }

    // --- final S_{T-1} term: v_127 lives in slot 1 / mbar 1 ---
    if (w == 0) MBAR_WAIT_CLUSTER(mb1, ph1);
    __syncthreads();
    {
        const float* cur = buf[1];
        unsigned long long ssp = 0;
        #pragma unroll
        for (int k = 0; k < 4; k++) {
            ulonglong2 aa = *(const ulonglong2*)&cur[4 * l + 128 * k];
            ADD2(ssp, ssp, aa.x); ADD2(ssp, ssp, aa.y);
        }
        float ss = hadd2(ssp);
        #pragma unroll
        for (int o = 16; o; o >>= 1) ss += __shfl_xor_sync(~0u, ss, o);
        if (rank == 0 && tid == 0) {
            L += __logf(ss);
            g_L[g] = L;
        }
    }
    // align exits: no CTA leaves while a peer could still target its smem
    asm volatile("barrier.cluster.arrive.aligned;" ::: "memory");
    asm volatile("barrier.cluster.wait.aligned;"   ::: "memory");
}

// ===================== K5: loss = -mean_b L[b] ===================================
__global__ void k_final(float* __restrict__ out) {
    if (threadIdx.x == 0) {
        float s = 0.f;
        #pragma unroll
        for (int i = 0; i < NB; i++) s += g_L[i];
        out[0] = -s / (float)NB;
    }
}

// ===================== launch ====================================================
extern "C" void kernel_launch(void* const* d_in, const int* in_sizes, int n_in,
                              void* d_out, int out_size) {
    const float* em = nullptr;
    const float* tm = nullptr;
    const float* p  = nullptr;
    const int* ids  = nullptr;
    for (int i = 0; i < n_in; i++) {
        if (in_sizes[i] == NB * NT)      ids = (const int*)d_in[i];
        else if (in_sizes[i] == NS * NV) em  = (const float*)d_in[i];
        else if (in_sizes[i] == NS * NS) tm  = (const float*)d_in[i];
        else if (in_sizes[i] == NS)      p   = (const float*)d_in[i];
    }

    k_lse_em<<<NS, 256>>>(em);
    k_tm_pi<<<NS + 1, 128>>>(tm, p);

    {
        cudaLaunchConfig_t cfg = {};
        cfg.gridDim  = dim3(NB * 8, 1, 1);
        cfg.blockDim = dim3(512, 1, 1);
        cfg.dynamicSmemBytes = 0;
        cfg.stream = 0;
        cudaLaunchAttribute attrs[1];
        attrs[0].id = cudaLaunchAttributeClusterDimension;
        attrs[0].val.clusterDim.x = 8;
        attrs[0].val.clusterDim.y = 1;
        attrs[0].val.clusterDim.z = 1;
        cfg.attrs = attrs;
        cfg.numAttrs = 1;
        cudaLaunchKernelEx(&cfg, k_forward, em, ids);
    }

    k_final<<<1, 32>>>((float*)d_out);
}

// round 15
// speedup vs baseline: 1.2054x; 1.2054x over previous
#include <cuda_runtime.h>
#include <cstdint>

#define NS 512
#define NV 32000
#define NB 16
#define NT 128

// ---- scratch (no cudaMalloc allowed) ----
__device__ float g_lse_em[NS];
__device__ float g_pi[NS];
__device__ float g_PT[NS * NS];          // PT[c][s] = softmax(tm)[s][c]
__device__ float g_E[NB * NT * NS];      // E[b][t][s] = exp(log_em[s, x_bt])
__device__ float g_L[NB];                // per-batch log-likelihood
__device__ unsigned g_done;              // completion counter for in-kernel final

// ---- helpers ----
__device__ __forceinline__ unsigned smem_u32(const void* p) {
    return (unsigned)__cvta_generic_to_shared(p);
}
__device__ __forceinline__ unsigned mapa_u32(unsigned local, unsigned rank) {
    unsigned r;
    asm("mapa.shared::cluster.u32 %0, %1, %2;" : "=r"(r) : "r"(local), "r"(rank));
    return r;
}
#define MBAR_INIT(mb, cnt) \
    asm volatile("mbarrier.init.shared.b64 [%0], %1;" :: "r"(mb), "r"(cnt) : "memory")
#define MBAR_EXPECT_TX(mb, bytes) \
    asm volatile("mbarrier.arrive.expect_tx.shared.b64 _, [%0], %1;" :: "r"(mb), "r"(bytes) : "memory")
// HW-sleep wait (suspend hint keeps spinners off the SMEM port)
#define MBAR_WAIT_CLUSTER(mb, parity) do {                                                       \
    asm volatile("{\n\t.reg .pred P;\n\tW%=:\n\t"                                                \
        "mbarrier.try_wait.parity.acquire.cluster.shared::cta.b64 P, [%0], %1, 0x989680;\n\t"    \
        "@!P bra W%=;\n\t}" :: "r"(mb), "r"(parity) : "memory");                                 \
} while (0)
__device__ __forceinline__ void st_async_v4(unsigned raddr, float4 v, unsigned rmbar) {
    asm volatile(
        "st.async.shared::cluster.mbarrier::complete_tx::bytes.v4.f32 "
        "[%0], {%1, %2, %3, %4}, [%5];"
        :: "r"(raddr), "f"(v.x), "f"(v.y), "f"(v.z), "f"(v.w), "r"(rmbar) : "memory");
}
// packed f32x2 math
#define FMA2(d, a, b, c) \
    asm("fma.rn.f32x2 %0, %1, %2, %3;" : "=l"(d) : "l"(a), "l"(b), "l"(c))
#define ADD2(d, a, b) \
    asm("add.rn.f32x2 %0, %1, %2;" : "=l"(d) : "l"(a), "l"(b))
__device__ __forceinline__ float hadd2(unsigned long long v) {
    float lo, hi;
    asm("mov.b64 {%0, %1}, %2;" : "=f"(lo), "=f"(hi) : "l"(v));
    return lo + hi;
}

// ===================== K1: row logsumexp of em [512, 32000] =====================
__global__ void k_lse_em(const float* __restrict__ em) {
    const int row = blockIdx.x;
    const float4* r = (const float4*)(em + (size_t)row * NV);
    const int n4 = NV / 4;  // 8000

    __shared__ float sm[8];

    float m = -1e30f;
    for (int i = threadIdx.x; i < n4; i += blockDim.x) {
        float4 x = r[i];
        m = fmaxf(m, fmaxf(fmaxf(x.x, x.y), fmaxf(x.z, x.w)));
    }
    #pragma unroll
    for (int o = 16; o; o >>= 1) m = fmaxf(m, __shfl_xor_sync(~0u, m, o));
    if ((threadIdx.x & 31) == 0) sm[threadIdx.x >> 5] = m;
    __syncthreads();
    if (threadIdx.x < 32) {
        float mm = (threadIdx.x < (blockDim.x >> 5)) ? sm[threadIdx.x] : -1e30f;
        #pragma unroll
        for (int o = 4; o; o >>= 1) mm = fmaxf(mm, __shfl_xor_sync(~0u, mm, o));
        if (threadIdx.x == 0) sm[0] = mm;
    }
    __syncthreads();
    m = sm[0];
    __syncthreads();

    float s = 0.f;
    for (int i = threadIdx.x; i < n4; i += blockDim.x) {
        float4 x = r[i];
        s += __expf(x.x - m) + __expf(x.y - m) + __expf(x.z - m) + __expf(x.w - m);
    }
    #pragma unroll
    for (int o = 16; o; o >>= 1) s += __shfl_xor_sync(~0u, s, o);
    if ((threadIdx.x & 31) == 0) sm[threadIdx.x >> 5] = s;
    __syncthreads();
    if (threadIdx.x == 0) {
        float tot = 0.f;
        for (int wi = 0; wi < (blockDim.x >> 5); wi++) tot += sm[wi];
        g_lse_em[row] = m + __logf(tot);
    }
}

// ===================== K2: P^T = softmax(tm) transposed; pi = softmax(p) ========
__global__ void k_tm_pi(const float* __restrict__ tm, const float* __restrict__ p) {
    __shared__ float sm[4];
    __shared__ float red;
    const int tid = threadIdx.x;  // 128 threads

    // reset the completion counter for this launch (stream-ordered before k_forward)
    if (blockIdx.x == NS && tid == 0) g_done = 0;

    const float* src = (blockIdx.x < NS) ? (tm + (size_t)blockIdx.x * NS) : p;

    float m = -1e30f;
    #pragma unroll
    for (int k = 0; k < 4; k++) m = fmaxf(m, src[tid + 128 * k]);
    #pragma unroll
    for (int o = 16; o; o >>= 1) m = fmaxf(m, __shfl_xor_sync(~0u, m, o));
    if ((tid & 31) == 0) sm[tid >> 5] = m;
    __syncthreads();
    if (tid == 0) red = fmaxf(fmaxf(sm[0], sm[1]), fmaxf(sm[2], sm[3]));
    __syncthreads();
    m = red;

    float s = 0.f;
    #pragma unroll
    for (int k = 0; k < 4; k++) s += __expf(src[tid + 128 * k] - m);
    #pragma unroll
    for (int o = 16; o; o >>= 1) s += __shfl_xor_sync(~0u, s, o);
    if ((tid & 31) == 0) sm[tid >> 5] = s;
    __syncthreads();
    if (tid == 0) red = m + __logf(sm[0] + sm[1] + sm[2] + sm[3]);
    __syncthreads();
    const float lse = red;

    if (blockIdx.x < NS) {
        const int row = blockIdx.x;  // source state s
        #pragma unroll
        for (int k = 0; k < 4; k++) {
            int c = tid + 128 * k;   // dest state
            g_PT[(size_t)c * NS + row] = __expf(src[c] - lse);
        }
    } else {
        #pragma unroll
        for (int k = 0; k < 4; k++) {
            int i = tid + 128 * k;
            g_pi[i] = __expf(p[i] - lse);
        }
    }
}

// ===================== K3: gather E[b][t][s] = exp(em[s, id] - lse_em[s]) =======
__global__ void k_gather(const float* __restrict__ em, const int* __restrict__ ids) {
    const int bt = blockIdx.x;           // 0..2047
    int id = ids[bt];
    id = (id < 0) ? 0 : ((id >= NV) ? NV - 1 : id);
    const float* col = em + id;
    #pragma unroll
    for (int k = 0; k < 4; k++) {
        int s = threadIdx.x + 128 * k;   // blockDim = 128
        g_E[(size_t)bt * NS + s] = __expf(col[(size_t)s * NV] - g_lse_em[s]);
    }
}

// ===================== K4: clustered scaled-forward recurrence ==================
// R12 core (best known: 221.7us) + ONE change: the final loss reduction is
// folded in (k_final deleted). Each cluster's (rank0, tid0) publishes g_L[g]
// with a release fence and atomically bumps g_done; the 16th arriver re-fences
// and writes -mean(L) straight to d_out.
__global__ void __cluster_dims__(8, 1, 1) __launch_bounds__(512, 1)
k_forward(float* __restrict__ out) {
    __shared__ __align__(16) float buf[2][NS];
    __shared__ __align__(8) unsigned long long mbars[2];

    const int tid = threadIdx.x;
    const int w = tid >> 5;
    const int l = tid & 31;
    unsigned rank;
    asm("mov.u32 %0, %%cluster_ctarank;" : "=r"(rank));
    const int g = blockIdx.x >> 3;                 // batch / cluster id
    const int colbase = (int)rank * 64 + w * 4;    // this warp's 4 columns

    // --- P^T chunk into packed registers ---
    unsigned long long Pa[4][4], Pb[4][4];
    #pragma unroll
    for (int j = 0; j < 4; j++)
        #pragma unroll
        for (int k = 0; k < 4; k++) {
            ulonglong2 pp = *(const ulonglong2*)&g_PT[(size_t)(colbase + j) * NS + 4 * l + 128 * k];
            Pa[j][k] = pp.x;
            Pb[j][k] = pp.y;
        }

    const unsigned mb0 = smem_u32(&mbars[0]);
    const unsigned mb1 = smem_u32(&mbars[1]);
    if (tid == 0) { MBAR_INIT(mb0, 1); MBAR_INIT(mb1, 1); }

    const float* Eb = g_E + (size_t)g * NT * NS;

    // --- t = 0: every CTA computes the full v0 = pi * E0 locally ---
    buf[0][tid] = g_pi[tid] * Eb[tid];
    __syncthreads();
    // peers' mbarriers must be initialized before any st.async targets them
    asm volatile("barrier.cluster.arrive.aligned;" ::: "memory");
    asm volatile("barrier.cluster.wait.aligned;"   ::: "memory");

    // --- per-lane remote addresses (lanes 0..7 push to peer = lane index) ---
    unsigned rbuf = 0, rmb0 = 0, rmb1 = 0;
    if (l < 8) {
        rbuf = mapa_u32(smem_u32(&buf[0][0]), (unsigned)l);
        rmb0 = mapa_u32(mb0, (unsigned)l);
        rmb1 = mapa_u32(mb1, (unsigned)l);
    }

    int ph0 = 0, ph1 = 0;
    float L = 0.f;
    float4 e4 = *(const float4*)&Eb[1 * NS + colbase];   // emission for t=1

    for (int t = 1; t < NT; t++) {
        const int sp = (t - 1) & 1;   // slot holding v_{t-1}
        const int sc = t & 1;         // slot receiving v_t

        // wait for v_{t-1}: ONLY warp 0 polls the mbarrier; bar.sync releases
        // (and memory-orders, cumulatively) the other 15 warps.
        if (t >= 2) {
            if (w == 0) {
                if (sp) MBAR_WAIT_CLUSTER(mb1, ph1);
                else    MBAR_WAIT_CLUSTER(mb0, ph0);
            }
            __syncthreads();
        }
        // arm this step's receive barrier (2048 B = 8 ranks x 16 warps x 16 B)
        if (tid == 0) MBAR_EXPECT_TX(sc ? mb1 : mb0, 2048u);

        // prefetch NEXT step's emission factors (off critical path)
        const int tn = (t + 1 < NT) ? t + 1 : t;
        const float4 e4n = *(const float4*)&Eb[tn * NS + colbase];

        // packed dot over the 512-vector + packed S_prev sum
        const float* cur = buf[sp];
        unsigned long long acc0 = 0, acc1 = 0, acc2 = 0, acc3 = 0, ssp = 0;
        #pragma unroll
        for (int k = 0; k < 4; k++) {
            ulonglong2 aa = *(const ulonglong2*)&cur[4 * l + 128 * k];
            FMA2(acc0, aa.x, Pa[0][k], acc0); FMA2(acc0, aa.y, Pb[0][k], acc0);
            FMA2(acc1, aa.x, Pa[1][k], acc1); FMA2(acc1, aa.y, Pb[1][k], acc1);
            FMA2(acc2, aa.x, Pa[2][k], acc2); FMA2(acc2, aa.y, Pb[2][k], acc2);
            FMA2(acc3, aa.x, Pa[3][k], acc3); FMA2(acc3, aa.y, Pb[3][k], acc3);
            ADD2(ssp, ssp, aa.x); ADD2(ssp, ssp, aa.y);
        }
        float a0 = hadd2(acc0), a1 = hadd2(acc1), a2 = hadd2(acc2), a3 = hadd2(acc3);
        float ss = hadd2(ssp);

        // reduce-scatter butterfly: octet o (= l>>3) ends holding full acc_o
        float p0 = (l & 16) ? a2 : a0;
        float q0 = (l & 16) ? a0 : a2;
        float p1 = (l & 16) ? a3 : a1;
        float q1 = (l & 16) ? a1 : a3;
        p0 += __shfl_xor_sync(~0u, q0, 16);
        p1 += __shfl_xor_sync(~0u, q1, 16);
        float pp = (l & 8) ? p1 : p0;
        float qq = (l & 8) ? p0 : p1;
        pp += __shfl_xor_sync(~0u, qq, 8);
        pp += __shfl_xor_sync(~0u, pp, 4);
        pp += __shfl_xor_sync(~0u, pp, 2);
        pp += __shfl_xor_sync(~0u, pp, 1);
        // regather: every lane builds (a0,a1,a2,a3) from octet representatives
        const int lb = l & 7;
        const float v0 = __shfl_sync(~0u, pp, lb);
        const float v1 = __shfl_sync(~0u, pp, 8 + lb);
        const float v2 = __shfl_sync(~0u, pp, 16 + lb);
        const float v3 = __shfl_sync(~0u, pp, 24 + lb);
        // full butterfly for ss (S_{t-1}; every lane needs it)
        #pragma unroll
        for (int o = 16; o; o >>= 1) ss += __shfl_xor_sync(~0u, ss, o);
        const float invS = __fdividef(1.f, ss);

        // push this warp's 4 scaled columns to all 8 CTAs (lane r -> peer r)
        if (l < 8) {
            float4 v;
            v.x = v0 * invS * e4.x;
            v.y = v1 * invS * e4.y;
            v.z = v2 * invS * e4.z;
            v.w = v3 * invS * e4.w;
            const unsigned daddr = rbuf + (unsigned)((sc * NS + colbase) * 4);
            st_async_v4(daddr, v, sc ? rmb1 : rmb0);
        }
        if (rank == 0 && tid == 0) L += __logf(ss);
        e4 = e4n;
        if (t >= 2) { if (sp) ph1 ^= 1; else ph0 ^= 1; }
    }

    // --- final S_{T-1} term: v_127 lives in slot 1 / mbar 1 ---
    if (w == 0) MBAR_WAIT_CLUSTER(mb1, ph1);
    __syncthreads();
    {
        const float* cur = buf[1];
        unsigned long long ssp = 0;
        #pragma unroll
        for (int k = 0; k < 4; k++) {
            ulonglong2 aa = *(const ulonglong2*)&cur[4 * l + 128 * k];
            ADD2(ssp, ssp, aa.x); ADD2(ssp, ssp, aa.y);
        }
        float ss = hadd2(ssp);
        #pragma unroll
        for (int o = 16; o; o >>= 1) ss += __shfl_xor_sync(~0u, ss, o);
        if (rank == 0 && tid == 0) {
            L += __logf(ss);
            g_L[g] = L;
            __threadfence();                     // publish g_L[g]
            unsigned old = atomicAdd(&g_done, 1u);
            if (old == NB - 1) {                 // last cluster: do the final reduce
                __threadfence();                 // acquire all g_L[]
                float s = 0.f;
                #pragma unroll
                for (int i = 0; i < NB; i++) s += g_L[i];
                out[0] = -s / (float)NB;
            }
        }
    }
    // align exits: no CTA leaves while a peer could still target its smem
    asm volatile("barrier.cluster.arrive.aligned;" ::: "memory");
    asm volatile("barrier.cluster.wait.aligned;"   ::: "memory");
}

// ===================== launch ====================================================
extern "C" void kernel_launch(void* const* d_in, const int* in_sizes, int n_in,
                              void* d_out, int out_size) {
    const float* em = nullptr;
    const float* tm = nullptr;
    const float* p  = nullptr;
    const int* ids  = nullptr;
    for (int i = 0; i < n_in; i++) {
        if (in_sizes[i] == NB * NT)      ids = (const int*)d_in[i];
        else if (in_sizes[i] == NS * NV) em  = (const float*)d_in[i];
        else if (in_sizes[i] == NS * NS) tm  = (const float*)d_in[i];
        else if (in_sizes[i] == NS)      p   = (const float*)d_in[i];
    }

    k_lse_em<<<NS, 256>>>(em);
    k_tm_pi<<<NS + 1, 128>>>(tm, p);
    k_gather<<<NB * NT, 128>>>(em, ids);

    {
        cudaLaunchConfig_t cfg = {};
        cfg.gridDim  = dim3(NB * 8, 1, 1);
        cfg.blockDim = dim3(512, 1, 1);
        cfg.dynamicSmemBytes = 0;
        cfg.stream = 0;
        cudaLaunchAttribute attrs[1];
        attrs[0].id = cudaLaunchAttributeClusterDimension;
        attrs[0].val.clusterDim.x = 8;
        attrs[0].val.clusterDim.y = 1;
        attrs[0].val.clusterDim.z = 1;
        cfg.attrs = attrs;
        cfg.numAttrs = 1;
        cudaLaunchKernelEx(&cfg, k_forward, (float*)d_out);
    }
}